// round 6
// baseline (speedup 1.0000x reference)
#include <cuda_runtime.h>
#include <cuda_bf16.h>

// ROI mean-pool, v6: split-column register scan (no SMEM scan round-trip),
// single __syncthreads, 8-lane-team box evaluation with free segment stitch.
//
// fmap:  [B=64, C=256, H=80, W=80] float32
// boxes: [B=64, N=100, 4] xyxy in [0,640]
// out:   [B, N, C] float32
//
// SMEM holds column prefix C[y][x]:
//   rows y=1..40  : true prefix (from plane rows 0..39),   at S[(y-1)*80]
//   rows y=41..80 : LOCAL prefix (plane rows 40..y-1),     at S[(y-1)*80]
//   C_true[y>=41] = local + C[40];  C[40] = S[39*80] (already in SMEM).
//   C[0] = zero row at S[6400].

#define Bn   64
#define Cn   256
#define Hn   80
#define Wn   80
#define Nn   100

__global__ __launch_bounds__(256, 6)
void roi_pool_v6_kernel(const float* __restrict__ fmap,
                        const float* __restrict__ boxes,
                        float* __restrict__ out)
{
    __shared__ __align__(16) float S[Hn * Wn + Wn];   // 25,920 B
    __shared__ int4 BC[Nn];                            // clipped box coords

    const int p   = blockIdx.x;                // plane id = b*Cn + c
    const int b   = p >> 8;
    const int c   = p & 255;
    const int tid = threadIdx.x;

    const float* __restrict__ plane = fmap + (size_t)p * (Hn * Wn);

    // ---- Phase 1 (one pass, one sync) ------------------------------------
    if (tid < 160) {
        // Threads 0..79: column tid, plane rows 0..39  -> C[1..40] (true).
        // Threads 80..159: column tid-80, plane rows 40..79 -> local prefix.
        const int col  = (tid < Wn) ? tid : tid - Wn;
        const int rowb = (tid < Wn) ? 0 : 40;
        const float* __restrict__ src = plane + rowb * Wn + col;
        float*       __restrict__ dst = S     + rowb * Wn + col;

        float acc = 0.0f;
        #pragma unroll 8
        for (int i = 0; i < 40; ++i) {
            acc += src[i * Wn];                // coalesced across lanes
            dst[i * Wn] = acc;                 // conflict-free STS
        }
    } else {
        // Threads 160..255: zero row + box-coord precompute (overlapped).
        const int t = tid - 160;               // 0..95
        if (t < Wn) S[Hn * Wn + t] = 0.0f;     // zero border row

        const float* __restrict__ bx = boxes + (size_t)b * (Nn * 4);
        #pragma unroll
        for (int n = t; n < Nn; n += 96) {
            float4 bb = reinterpret_cast<const float4*>(bx)[n];
            // Match JAX exactly: IEEE div by 640, IEEE mul by 80, trunc, clip.
            int x1 = min(max((int)(__fmul_rn(__fdiv_rn(bb.x, 640.0f), 80.0f)), 0), Wn);
            int y1 = min(max((int)(__fmul_rn(__fdiv_rn(bb.y, 640.0f), 80.0f)), 0), Hn);
            int x2 = min(max((int)(__fmul_rn(__fdiv_rn(bb.z, 640.0f), 80.0f)), 0), Wn);
            int y2 = min(max((int)(__fmul_rn(__fdiv_rn(bb.w, 640.0f), 80.0f)), 0), Hn);
            BC[n] = make_int4(x1, y1, x2, y2);
        }
    }
    __syncthreads();

    // ---- Phase 2: 8-lane team per box ------------------------------------
    // C[y] (y>=1) at S[(y-1)*80]; C[0] = zero row. Boxes with y1<=40<y2 add
    // the segment-B offset row C[40] = S[39*80] inside the loop.
    const int team = tid >> 3;                 // 0..31
    const int tl   = tid & 7;
    float* __restrict__ ob = out + (size_t)b * (Nn * Cn) + c;
    const float* __restrict__ zrow = &S[Hn * Wn];
    const float* __restrict__ trow = &S[39 * Wn];   // C[40]

    for (int n = team; n < Nn; n += 32) {
        int4 q = BC[n];                        // x1,y1,x2,y2
        const float* __restrict__ r2 = (q.w > 0) ? &S[(q.w - 1) * Wn] : zrow;
        const float* __restrict__ r1 = (q.y > 0) ? &S[(q.y - 1) * Wn] : zrow;
        const bool straddle = (q.y <= 40) && (q.w >= 41);

        float s = 0.0f;
        if (straddle) {
            for (int x = q.x + tl; x < q.z; x += 8)
                s += r2[x] - r1[x] + trow[x];
        } else {
            for (int x = q.x + tl; x < q.z; x += 8)
                s += r2[x] - r1[x];
        }

        // width-8 tree reduce (3 shuffles). N%4==0 -> all teams of a warp
        // share loop-trip validity, full-mask shuffles are safe.
        s += __shfl_down_sync(0xFFFFFFFFu, s, 4, 8);
        s += __shfl_down_sync(0xFFFFFFFFu, s, 2, 8);
        s += __shfl_down_sync(0xFFFFFFFFu, s, 1, 8);

        if (tl == 0) {
            int dy = q.w - q.y;
            int dx = q.z - q.x;
            bool valid = (dy > 0) && (dx > 0);
            int  area  = max(dy * dx, 1);
            ob[(size_t)n * Cn] = valid ? s / (float)area : 0.0f;
        }
    }
}

extern "C" void kernel_launch(void* const* d_in, const int* in_sizes, int n_in,
                              void* d_out, int out_size)
{
    const float* fmap  = (const float*)d_in[0];   // [64,256,80,80]
    const float* boxes = (const float*)d_in[1];   // [64,100,4]
    float*       out   = (float*)d_out;           // [64,100,256]

    (void)in_sizes; (void)n_in; (void)out_size;

    roi_pool_v6_kernel<<<Bn * Cn, 256>>>(fmap, boxes, out);
}